// round 1
// baseline (speedup 1.0000x reference)
#include <cuda_runtime.h>

namespace {
constexpr int B_ = 512, M_ = 8, S_ = 4, K_ = 64, TH_ = 16, Z_ = 16, H_ = 16;
constexpr float LOG2PI = 1.8378770664093453f;
}

__device__ int g_mask_mode;  // 0 = int32, 1 = uint8, 2 = float32

// Classify the storage dtype of the bool nan_mask. Reads only 4096 bytes
// (the minimum possible buffer size across all candidate dtypes).
__global__ void detect_mask_kernel(const unsigned char* __restrict__ p) {
    __shared__ int sWordBad, sAnyFOne, sOffByte;
    int tid = threadIdx.x;
    if (tid == 0) { sWordBad = 0; sAnyFOne = 0; sOffByte = 0; }
    __syncthreads();
    const unsigned int* w = (const unsigned int*)p;
#pragma unroll
    for (int q = 0; q < 4; q++) {
        unsigned int v = w[tid * 4 + q];
        if (v != 0u && v != 0x3F800000u) sWordBad = 1;
        if (v == 0x3F800000u) sAnyFOne = 1;
    }
#pragma unroll
    for (int q = 0; q < 16; q++) {
        int off = tid * 16 + q;
        if ((off & 3) && p[off]) sOffByte = 1;
    }
    __syncthreads();
    if (tid == 0) {
        // float32 pattern: every word is 0.0f or 1.0f bits, at least one 1.0f
        // uint8 pattern: some nonzero byte at a non-word-aligned offset
        // otherwise int32 (0/1 words)
        g_mask_mode = (!sWordBad && sAnyFOne) ? 2 : (sOffByte ? 1 : 0);
    }
}

// Energy for CNT compacted m-rows: sum_i e3 . relu(e2 @ relu(tpart[i]+zp) + e2b)
template <int CNT>
__device__ __forceinline__ float energy_chunk(
    int base, const float zp[16],
    const float (*__restrict__ tpart)[16],
    const float (*__restrict__ e2w)[16],
    const float* __restrict__ e2b,
    const float* __restrict__ e3w)
{
    float h1[CNT][16];
#pragma unroll
    for (int i = 0; i < CNT; i++) {
        const float4* tp = (const float4*)tpart[base + i];
#pragma unroll
        for (int q = 0; q < 4; q++) {
            float4 t = tp[q];
            h1[i][4*q+0] = fmaxf(t.x + zp[4*q+0], 0.f);
            h1[i][4*q+1] = fmaxf(t.y + zp[4*q+1], 0.f);
            h1[i][4*q+2] = fmaxf(t.z + zp[4*q+2], 0.f);
            h1[i][4*q+3] = fmaxf(t.w + zp[4*q+3], 0.f);
        }
    }
    float en[CNT];
#pragma unroll
    for (int i = 0; i < CNT; i++) en[i] = 0.f;
#pragma unroll
    for (int g = 0; g < 16; g++) {
        float bias = e2b[g];
        float acc[CNT];
#pragma unroll
        for (int i = 0; i < CNT; i++) acc[i] = bias;
        const float4* wr = (const float4*)e2w[g];
#pragma unroll
        for (int q = 0; q < 4; q++) {
            float4 wv = wr[q];
#pragma unroll
            for (int i = 0; i < CNT; i++) {
                acc[i] = fmaf(wv.x, h1[i][4*q+0], acc[i]);
                acc[i] = fmaf(wv.y, h1[i][4*q+1], acc[i]);
                acc[i] = fmaf(wv.z, h1[i][4*q+2], acc[i]);
                acc[i] = fmaf(wv.w, h1[i][4*q+3], acc[i]);
            }
        }
        float w3 = e3w[g];
#pragma unroll
        for (int i = 0; i < CNT; i++) en[i] = fmaf(w3, fmaxf(acc[i], 0.f), en[i]);
    }
    float tot = 0.f;
#pragma unroll
    for (int i = 0; i < CNT; i++) tot += en[i];
    return tot;
}

__device__ __forceinline__ float energy_dispatch(
    int base, int cnt, const float zp[16],
    const float (*tpart)[16], const float (*e2w)[16],
    const float* e2b, const float* e3w)
{
    switch (cnt) {
        case 1: return energy_chunk<1>(base, zp, tpart, e2w, e2b, e3w);
        case 2: return energy_chunk<2>(base, zp, tpart, e2w, e2b, e3w);
        case 3: return energy_chunk<3>(base, zp, tpart, e2w, e2b, e3w);
        case 4: return energy_chunk<4>(base, zp, tpart, e2w, e2b, e3w);
        default: return 0.f;
    }
}

__global__ void __launch_bounds__(256) ebm_kernel(
    const float* __restrict__ thetas,
    const void*  __restrict__ nan_mask,
    const float* __restrict__ eps,
    const float* __restrict__ gumbel,
    const float* __restrict__ pi1_w,   const float* __restrict__ pi1_b,
    const float* __restrict__ pimu_w,  const float* __restrict__ pimu_b,
    const float* __restrict__ piprec_w,const float* __restrict__ piprec_b,
    const float* __restrict__ e1_w,    const float* __restrict__ e1_b,
    const float* __restrict__ e2_w,    const float* __restrict__ e2_b,
    const float* __restrict__ e3_w,    const float* __restrict__ e3_b,
    float* __restrict__ out)
{
    const int b = blockIdx.x;
    const int tid = threadIdx.x;

    __shared__ __align__(16) float sh_theta[M_][TH_];       // thetas[b]
    __shared__ __align__(16) float sh_e1w[H_][TH_ + Z_];    // [h][0:16]=W_t, [h][16:32]=W_z
    __shared__ __align__(16) float sh_e2w[H_][H_];
    __shared__ __align__(16) float sh_tpart[M_][H_];        // compacted valid m
    __shared__ float sh_e1b[H_], sh_e2b[H_], sh_e3w[H_];
    __shared__ float sh_mu[Z_], sh_std[Z_];
    __shared__ float sh_tsum[TH_], sh_h[H_];
    __shared__ float sh_logstd_sum, sh_e3b0;
    __shared__ int   sh_mv, sh_midx[M_];
    __shared__ float sh_logits[S_ * K_], sh_logiw[S_ * K_], sh_energy[S_ * K_];

    // ---- cooperative loads ----
    if (tid < 128) ((float*)sh_theta)[tid] = thetas[b * 128 + tid];
    ((float*)sh_e1w)[tid]       = e1_w[tid];
    ((float*)sh_e1w)[tid + 256] = e1_w[tid + 256];
    ((float*)sh_e2w)[tid]       = e2_w[tid];
    if (tid < 16) {
        sh_e1b[tid] = e1_b[tid];
        sh_e2b[tid] = e2_b[tid];
        sh_e3w[tid] = e3_w[tid];
    }
    if (tid == 16) sh_e3b0 = e3_b[0];
    if (tid == 17) {
        // mask compaction: keep m where nan_mask is false
        int mode = g_mask_mode;
        int mv = 0;
#pragma unroll
        for (int m = 0; m < M_; m++) {
            bool masked;
            if (mode == 1)      masked = ((const unsigned char*)nan_mask)[b * M_ + m] != 0;
            else if (mode == 2) masked = ((const float*)nan_mask)[b * M_ + m] != 0.f;
            else                masked = ((const int*)nan_mask)[b * M_ + m] != 0;
            if (!masked) sh_midx[mv++] = m;
        }
        sh_mv = mv;
    }
    __syncthreads();

    // ---- per-b prior head: theta_sum -> h -> mu/prec -> mu_eff/std ----
    if (tid < 16) {
        float s = 0.f;
#pragma unroll
        for (int m = 0; m < M_; m++) s += sh_theta[m][tid];
        sh_tsum[tid] = s;
    }
    __syncthreads();
    if (tid < 16) {
        float a = __ldg(&pi1_b[tid]);
#pragma unroll
        for (int t = 0; t < 16; t++) a = fmaf(__ldg(&pi1_w[tid * 16 + t]), sh_tsum[t], a);
        sh_h[tid] = fmaxf(a, 0.f);
    }
    __syncthreads();
    if (tid < 16) {
        float mu = __ldg(&pimu_b[tid]), lp = __ldg(&piprec_b[tid]);
#pragma unroll
        for (int j = 0; j < 16; j++) {
            float hj = sh_h[j];
            mu = fmaf(__ldg(&pimu_w[tid * 16 + j]), hj, mu);
            lp = fmaf(__ldg(&piprec_w[tid * 16 + j]), hj, lp);
        }
        float prec = expf(lp) + 0.01f;
        float var  = 1.f / (1.f + prec);
        float stdv = sqrtf(var);
        sh_mu[tid]  = var * prec * mu;
        sh_std[tid] = stdv;
        float ls = logf(stdv);
#pragma unroll
        for (int o = 8; o; o >>= 1) ls += __shfl_down_sync(0x0000ffffu, ls, o);
        if (tid == 0) sh_logstd_sum = ls;
    }
    __syncthreads();

    // ---- t_part for compacted m rows ----
    if (tid < 128) {
        int i = tid >> 4, j = tid & 15;
        if (i < sh_mv) {
            int m = sh_midx[i];
            float a = 0.f;
#pragma unroll
            for (int t = 0; t < 16; t++) a = fmaf(sh_theta[m][t], sh_e1w[j][t], a);
            sh_tpart[i][j] = a;
        }
    }
    __syncthreads();

    // ---- main: one thread per (s,k) ----
    const int s = tid >> 6, k = tid & 63;
    const float* ep = eps + ((size_t)((s * K_ + k) * B_ + b)) * Z_;
    float ev[16];
    {
        const float4* e4 = (const float4*)ep;
#pragma unroll
        for (int q = 0; q < 4; q++) {
            float4 v = __ldg(&e4[q]);
            ev[4*q+0] = v.x; ev[4*q+1] = v.y; ev[4*q+2] = v.z; ev[4*q+3] = v.w;
        }
    }
    float zv[16];
    float eps2 = 0.f, z2 = 0.f;
#pragma unroll
    for (int zi = 0; zi < 16; zi++) {
        float e = ev[zi];
        float z = fmaf(sh_std[zi], e, sh_mu[zi]);
        zv[zi] = z;
        eps2 = fmaf(e, e, eps2);
        z2   = fmaf(z, z, z2);
    }
    float pi_lp = -0.5f * eps2 - sh_logstd_sum - 8.f * LOG2PI;
    float prior = -0.5f * z2 - 8.f * LOG2PI;

    // z_part = W_z @ z + e1_b
    float zp[16];
#pragma unroll
    for (int h = 0; h < 16; h++) {
        float a = sh_e1b[h];
        const float4* wr = (const float4*)&sh_e1w[h][16];
#pragma unroll
        for (int q = 0; q < 4; q++) {
            float4 w = wr[q];
            a = fmaf(w.x, zv[4*q+0], a);
            a = fmaf(w.y, zv[4*q+1], a);
            a = fmaf(w.z, zv[4*q+2], a);
            a = fmaf(w.w, zv[4*q+3], a);
        }
        zp[h] = a;
    }

    const int mv = sh_mv;
    float energy = 0.f;
    int c0 = mv < 4 ? mv : 4;
    if (c0 > 0)  energy += energy_dispatch(0, c0, zp, sh_tpart, sh_e2w, sh_e2b, sh_e3w);
    if (mv > 4)  energy += energy_dispatch(4, mv - 4, zp, sh_tpart, sh_e2w, sh_e2b, sh_e3w);
    energy += (float)mv * sh_e3b0;

    float liw = prior - energy - pi_lp;
    float u = __ldg(&gumbel[(b * S_ + s) * K_ + k]);
    float gum = -logf(-logf(u + 1e-20f) + 1e-20f);

    sh_logiw[tid]  = liw;
    sh_logits[tid] = liw + gum;
    sh_energy[tid] = energy;
    __syncthreads();

    // ---- per-s reduction: argmax(logits), logsumexp(log_iws) ----
    const int warp = tid >> 5, lane = tid & 31;
    if (warp < S_) {
        const int ss = warp;
        const float* L = &sh_logits[ss * 64];
        float v0 = L[lane], v1 = L[lane + 32];
        float bv; int bi;
        if (v0 >= v1) { bv = v0; bi = lane; } else { bv = v1; bi = lane + 32; }
#pragma unroll
        for (int o = 16; o; o >>= 1) {
            float ov = __shfl_down_sync(0xffffffffu, bv, o);
            int   oi = __shfl_down_sync(0xffffffffu, bi, o);
            if (ov > bv || (ov == bv && oi < bi)) { bv = ov; bi = oi; }
        }
        int kstar = __shfl_sync(0xffffffffu, bi, 0);

        const float* LW = &sh_logiw[ss * 64];
        float l0 = LW[lane], l1 = LW[lane + 32];
        float mx = fmaxf(l0, l1);
#pragma unroll
        for (int o = 16; o; o >>= 1) mx = fmaxf(mx, __shfl_down_sync(0xffffffffu, mx, o));
        mx = __shfl_sync(0xffffffffu, mx, 0);
        float se = expf(l0 - mx) + expf(l1 - mx);
#pragma unroll
        for (int o = 16; o; o >>= 1) se += __shfl_down_sync(0xffffffffu, se, o);

        if (lane == 0) {
            float lse  = mx + logf(se);
            float lavg = lse - logf((float)K_);
            float ez   = sh_energy[ss * 64 + kstar];
            out[B_ * S_ * Z_ + b * S_ + ss] = -ez - lavg;
        }
        if (lane < 16) {
            float e = __ldg(&eps[((size_t)((ss * K_ + kstar) * B_ + b)) * Z_ + lane]);
            out[(b * S_ + ss) * Z_ + lane] = fmaf(sh_std[lane], e, sh_mu[lane]);
        }
    }
}

extern "C" void kernel_launch(void* const* d_in, const int* in_sizes, int n_in,
                              void* d_out, int out_size) {
    // inputs: thetas, nan_mask, eps, gumbel_u, [n_samples], pi1_w, pi1_b,
    //         pimu_w, pimu_b, piprec_w, piprec_b, e1_w, e1_b, e2_w, e2_b, e3_w, e3_b
    const float* thetas   = (const float*)d_in[0];
    const void*  nan_mask = d_in[1];
    const float* eps      = (const float*)d_in[2];
    const float* gumbel   = (const float*)d_in[3];
    // n_samples may or may not be materialized as a device array (size 1)
    int base = (n_in >= 17 && in_sizes[4] == 1) ? 5 : 4;
    const float* pi1_w    = (const float*)d_in[base + 0];
    const float* pi1_b    = (const float*)d_in[base + 1];
    const float* pimu_w   = (const float*)d_in[base + 2];
    const float* pimu_b   = (const float*)d_in[base + 3];
    const float* piprec_w = (const float*)d_in[base + 4];
    const float* piprec_b = (const float*)d_in[base + 5];
    const float* e1_w     = (const float*)d_in[base + 6];
    const float* e1_b     = (const float*)d_in[base + 7];
    const float* e2_w     = (const float*)d_in[base + 8];
    const float* e2_b     = (const float*)d_in[base + 9];
    const float* e3_w     = (const float*)d_in[base + 10];
    const float* e3_b     = (const float*)d_in[base + 11];

    detect_mask_kernel<<<1, 256>>>((const unsigned char*)nan_mask);
    ebm_kernel<<<B_, 256>>>(thetas, nan_mask, eps, gumbel,
                            pi1_w, pi1_b, pimu_w, pimu_b, piprec_w, piprec_b,
                            e1_w, e1_b, e2_w, e2_b, e3_w, e3_b,
                            (float*)d_out);
}

// round 2
// speedup vs baseline: 5.6477x; 5.6477x over previous
#include <cuda_runtime.h>

namespace {
constexpr int B_ = 512, M_ = 8, S_ = 4, K_ = 64, TH_ = 16, Z_ = 16, H_ = 16;
constexpr float LOG2PI = 1.8378770664093453f;
}

__device__ int g_mask_mode;  // 0 = int32, 1 = uint8, 2 = float32

// Classify the storage dtype of the bool nan_mask. Reads only 4096 bytes
// (the minimum possible buffer size across all candidate dtypes).
__global__ void detect_mask_kernel(const unsigned char* __restrict__ p) {
    __shared__ int sWordBad, sAnyFOne, sOffByte;
    int tid = threadIdx.x;
    if (tid == 0) { sWordBad = 0; sAnyFOne = 0; sOffByte = 0; }
    __syncthreads();
    const unsigned int* w = (const unsigned int*)p;
#pragma unroll
    for (int q = 0; q < 4; q++) {
        unsigned int v = w[tid * 4 + q];
        if (v != 0u && v != 0x3F800000u) sWordBad = 1;
        if (v == 0x3F800000u) sAnyFOne = 1;
    }
#pragma unroll
    for (int q = 0; q < 16; q++) {
        int off = tid * 16 + q;
        if ((off & 3) && p[off]) sOffByte = 1;
    }
    __syncthreads();
    if (tid == 0) {
        g_mask_mode = (!sWordBad && sAnyFOne) ? 2 : (sOffByte ? 1 : 0);
    }
}

__global__ void __launch_bounds__(256, 1) ebm_kernel(
    const float* __restrict__ thetas,
    const void*  __restrict__ nan_mask,
    const float* __restrict__ eps,
    const float* __restrict__ gumbel,
    const float* __restrict__ pi1_w,   const float* __restrict__ pi1_b,
    const float* __restrict__ pimu_w,  const float* __restrict__ pimu_b,
    const float* __restrict__ piprec_w,const float* __restrict__ piprec_b,
    const float* __restrict__ e1_w,    const float* __restrict__ e1_b,
    const float* __restrict__ e2_w,    const float* __restrict__ e2_b,
    const float* __restrict__ e3_w,    const float* __restrict__ e3_b,
    float* __restrict__ out)
{
    const int b = blockIdx.x;
    const int tid = threadIdx.x;

    __shared__ __align__(16) float sh_theta[M_][TH_];       // thetas[b]
    __shared__ __align__(16) float sh_e1w[H_][TH_ + Z_];    // [h][0:16]=W_t, [h][16:32]=W_z
    __shared__ __align__(16) float sh_e2w[H_][H_];
    __shared__ __align__(16) float sh_tpart[M_][H_];        // compacted valid m
    __shared__ float sh_e1b[H_], sh_e2b[H_], sh_e3w[H_];
    __shared__ float sh_mu[Z_], sh_std[Z_];
    __shared__ float sh_tsum[TH_], sh_h[H_];
    __shared__ float sh_logstd_sum, sh_e3b0;
    __shared__ int   sh_mv, sh_midx[M_];
    __shared__ float sh_logits[S_ * K_], sh_logiw[S_ * K_], sh_energy[S_ * K_];

    // ---- cooperative loads ----
    if (tid < 128) ((float*)sh_theta)[tid] = thetas[b * 128 + tid];
    ((float*)sh_e1w)[tid]       = e1_w[tid];
    ((float*)sh_e1w)[tid + 256] = e1_w[tid + 256];
    ((float*)sh_e2w)[tid]       = e2_w[tid];
    if (tid < 16) {
        sh_e1b[tid] = e1_b[tid];
        sh_e2b[tid] = e2_b[tid];
        sh_e3w[tid] = e3_w[tid];
    }
    if (tid == 16) sh_e3b0 = e3_b[0];
    if (tid == 17) {
        int mode = g_mask_mode;
        int mv = 0;
#pragma unroll
        for (int m = 0; m < M_; m++) {
            bool masked;
            if (mode == 1)      masked = ((const unsigned char*)nan_mask)[b * M_ + m] != 0;
            else if (mode == 2) masked = ((const float*)nan_mask)[b * M_ + m] != 0.f;
            else                masked = ((const int*)nan_mask)[b * M_ + m] != 0;
            if (!masked) sh_midx[mv++] = m;
        }
        sh_mv = mv;
    }
    __syncthreads();

    // ---- per-b prior head ----
    if (tid < 16) {
        float s = 0.f;
#pragma unroll
        for (int m = 0; m < M_; m++) s += sh_theta[m][tid];
        sh_tsum[tid] = s;
    }
    __syncthreads();
    if (tid < 16) {
        float a = __ldg(&pi1_b[tid]);
#pragma unroll
        for (int t = 0; t < 16; t++) a = fmaf(__ldg(&pi1_w[tid * 16 + t]), sh_tsum[t], a);
        sh_h[tid] = fmaxf(a, 0.f);
    }
    __syncthreads();
    if (tid < 16) {
        float mu = __ldg(&pimu_b[tid]), lp = __ldg(&piprec_b[tid]);
#pragma unroll
        for (int j = 0; j < 16; j++) {
            float hj = sh_h[j];
            mu = fmaf(__ldg(&pimu_w[tid * 16 + j]), hj, mu);
            lp = fmaf(__ldg(&piprec_w[tid * 16 + j]), hj, lp);
        }
        float prec = expf(lp) + 0.01f;
        float var  = 1.f / (1.f + prec);
        float stdv = sqrtf(var);
        sh_mu[tid]  = var * prec * mu;
        sh_std[tid] = stdv;
        float ls = logf(stdv);
#pragma unroll
        for (int o = 8; o; o >>= 1) ls += __shfl_down_sync(0x0000ffffu, ls, o);
        if (tid == 0) sh_logstd_sum = ls;
    }
    __syncthreads();

    // ---- t_part for compacted m rows ----
    if (tid < 128) {
        int i = tid >> 4, j = tid & 15;
        if (i < sh_mv) {
            int m = sh_midx[i];
            float a = 0.f;
#pragma unroll
            for (int t = 0; t < 16; t++) a = fmaf(sh_theta[m][t], sh_e1w[j][t], a);
            sh_tpart[i][j] = a;
        }
    }
    __syncthreads();

    // ---- main: one thread per (s,k) ----
    const int s = tid >> 6, k = tid & 63;
    const float* ep = eps + ((size_t)((s * K_ + k) * B_ + b)) * Z_;
    float zv[16];
    float eps2 = 0.f, z2 = 0.f;
    {
        const float4* e4 = (const float4*)ep;
#pragma unroll
        for (int q = 0; q < 4; q++) {
            float4 v = __ldg(&e4[q]);
            float e0 = v.x, e1 = v.y, e2 = v.z, e3 = v.w;
            float z0 = fmaf(sh_std[4*q+0], e0, sh_mu[4*q+0]);
            float z1 = fmaf(sh_std[4*q+1], e1, sh_mu[4*q+1]);
            float z2v = fmaf(sh_std[4*q+2], e2, sh_mu[4*q+2]);
            float z3 = fmaf(sh_std[4*q+3], e3, sh_mu[4*q+3]);
            zv[4*q+0] = z0; zv[4*q+1] = z1; zv[4*q+2] = z2v; zv[4*q+3] = z3;
            eps2 = fmaf(e0, e0, eps2); eps2 = fmaf(e1, e1, eps2);
            eps2 = fmaf(e2, e2, eps2); eps2 = fmaf(e3, e3, eps2);
            z2 = fmaf(z0, z0, z2); z2 = fmaf(z1, z1, z2);
            z2 = fmaf(z2v, z2v, z2); z2 = fmaf(z3, z3, z2);
        }
    }
    float pi_lp = -0.5f * eps2 - sh_logstd_sum - 8.f * LOG2PI;
    float prior = -0.5f * z2 - 8.f * LOG2PI;

    // z_part = W_z @ z + e1_b
    float zp[16];
#pragma unroll
    for (int h = 0; h < 16; h++) {
        float a = sh_e1b[h];
        const float4* wr = (const float4*)&sh_e1w[h][16];
#pragma unroll
        for (int q = 0; q < 4; q++) {
            float4 w = wr[q];
            a = fmaf(w.x, zv[4*q+0], a);
            a = fmaf(w.y, zv[4*q+1], a);
            a = fmaf(w.z, zv[4*q+2], a);
            a = fmaf(w.w, zv[4*q+3], a);
        }
        zp[h] = a;
    }

    // ---- energy: dynamic loop over compacted m rows (uniform per block).
    // h1[16] lives briefly in registers and is consumed immediately — no spills.
    const int mv = sh_mv;
    float energy = (float)mv * sh_e3b0;
    for (int i = 0; i < mv; i++) {
        float h1[16];
        const float4* tp = (const float4*)sh_tpart[i];
#pragma unroll
        for (int q = 0; q < 4; q++) {
            float4 t = tp[q];
            h1[4*q+0] = fmaxf(t.x + zp[4*q+0], 0.f);
            h1[4*q+1] = fmaxf(t.y + zp[4*q+1], 0.f);
            h1[4*q+2] = fmaxf(t.z + zp[4*q+2], 0.f);
            h1[4*q+3] = fmaxf(t.w + zp[4*q+3], 0.f);
        }
#pragma unroll
        for (int g = 0; g < 16; g++) {
            float acc = sh_e2b[g];
            const float4* wr = (const float4*)sh_e2w[g];
#pragma unroll
            for (int q = 0; q < 4; q++) {
                float4 w = wr[q];
                acc = fmaf(w.x, h1[4*q+0], acc);
                acc = fmaf(w.y, h1[4*q+1], acc);
                acc = fmaf(w.z, h1[4*q+2], acc);
                acc = fmaf(w.w, h1[4*q+3], acc);
            }
            energy = fmaf(sh_e3w[g], fmaxf(acc, 0.f), energy);
        }
    }

    float liw = prior - energy - pi_lp;
    float u = __ldg(&gumbel[(b * S_ + s) * K_ + k]);
    float gum = -logf(-logf(u + 1e-20f) + 1e-20f);

    sh_logiw[tid]  = liw;
    sh_logits[tid] = liw + gum;
    sh_energy[tid] = energy;
    __syncthreads();

    // ---- per-s reduction: argmax(logits), logsumexp(log_iws) ----
    const int warp = tid >> 5, lane = tid & 31;
    if (warp < S_) {
        const int ss = warp;
        const float* L = &sh_logits[ss * 64];
        float v0 = L[lane], v1 = L[lane + 32];
        float bv; int bi;
        if (v0 >= v1) { bv = v0; bi = lane; } else { bv = v1; bi = lane + 32; }
#pragma unroll
        for (int o = 16; o; o >>= 1) {
            float ov = __shfl_down_sync(0xffffffffu, bv, o);
            int   oi = __shfl_down_sync(0xffffffffu, bi, o);
            if (ov > bv || (ov == bv && oi < bi)) { bv = ov; bi = oi; }
        }
        int kstar = __shfl_sync(0xffffffffu, bi, 0);

        const float* LW = &sh_logiw[ss * 64];
        float l0 = LW[lane], l1 = LW[lane + 32];
        float mx = fmaxf(l0, l1);
#pragma unroll
        for (int o = 16; o; o >>= 1) mx = fmaxf(mx, __shfl_down_sync(0xffffffffu, mx, o));
        mx = __shfl_sync(0xffffffffu, mx, 0);
        float se = expf(l0 - mx) + expf(l1 - mx);
#pragma unroll
        for (int o = 16; o; o >>= 1) se += __shfl_down_sync(0xffffffffu, se, o);

        if (lane == 0) {
            float lse  = mx + logf(se);
            float lavg = lse - logf((float)K_);
            float ez   = sh_energy[ss * 64 + kstar];
            out[B_ * S_ * Z_ + b * S_ + ss] = -ez - lavg;
        }
        if (lane < 16) {
            float e = __ldg(&eps[((size_t)((ss * K_ + kstar) * B_ + b)) * Z_ + lane]);
            out[(b * S_ + ss) * Z_ + lane] = fmaf(sh_std[lane], e, sh_mu[lane]);
        }
    }
}

extern "C" void kernel_launch(void* const* d_in, const int* in_sizes, int n_in,
                              void* d_out, int out_size) {
    const float* thetas   = (const float*)d_in[0];
    const void*  nan_mask = d_in[1];
    const float* eps      = (const float*)d_in[2];
    const float* gumbel   = (const float*)d_in[3];
    int base = (n_in >= 17 && in_sizes[4] == 1) ? 5 : 4;
    const float* pi1_w    = (const float*)d_in[base + 0];
    const float* pi1_b    = (const float*)d_in[base + 1];
    const float* pimu_w   = (const float*)d_in[base + 2];
    const float* pimu_b   = (const float*)d_in[base + 3];
    const float* piprec_w = (const float*)d_in[base + 4];
    const float* piprec_b = (const float*)d_in[base + 5];
    const float* e1_w     = (const float*)d_in[base + 6];
    const float* e1_b     = (const float*)d_in[base + 7];
    const float* e2_w     = (const float*)d_in[base + 8];
    const float* e2_b     = (const float*)d_in[base + 9];
    const float* e3_w     = (const float*)d_in[base + 10];
    const float* e3_b     = (const float*)d_in[base + 11];

    detect_mask_kernel<<<1, 256>>>((const unsigned char*)nan_mask);
    ebm_kernel<<<B_, 256>>>(thetas, nan_mask, eps, gumbel,
                            pi1_w, pi1_b, pimu_w, pimu_b, piprec_w, piprec_b,
                            e1_w, e1_b, e2_w, e2_b, e3_w, e3_b,
                            (float*)d_out);
}